// round 8
// baseline (speedup 1.0000x reference)
#include <cuda_runtime.h>
#include <cuda_bf16.h>

#define TT 512
#define BB 32
#define VV 8000
#define LL 100
#define SS (2*LL+1)   // 201
#define NEGF (-1e30f)
#define LOG2E 1.4426950408889634f
#define LN2   0.6931471805599453f

#define SWARPS 8      // scan warps per sample
#define OWN   28      // owned states per warp (lanes 4..31)
#define DEPTH 4       // lp prefetch depth (pairs) -- compile-time indexed only

#define NSCAN BB              // 32 consumer blocks
#define NPROD (TT*BB)         // 16384 producer blocks (one row each)
#define NBLK  (NSCAN + NPROD)

// Scratch (allocation-free rule: __device__ globals)
__device__ float g_lp[TT*BB*SS];      // 13.2 MB, log2-domain emissions
__device__ int   g_flags[TT*BB];      // row-ready flags (== epoch when ready)
__device__ int   g_epoch;

__device__ __forceinline__ float ex2f(float x) {
    float r; asm("ex2.approx.ftz.f32 %0, %1;" : "=f"(r) : "f"(x)); return r;
}
__device__ __forceinline__ float lg2f(float x) {
    float r; asm("lg2.approx.ftz.f32 %0, %1;" : "=f"(r) : "f"(x)); return r;
}
__device__ __forceinline__ int ld_acq(const int* p) {
    int v; asm volatile("ld.acquire.gpu.b32 %0, [%1];" : "=r"(v) : "l"(p) : "memory"); return v;
}
__device__ __forceinline__ void st_rel(int* p, int v) {
    asm volatile("st.release.gpu.b32 [%0], %1;" :: "l"(p), "r"(v) : "memory");
}

// ---------------------------------------------------------------------------
__global__ void init_kernel(float* __restrict__ out) {
    g_epoch = g_epoch + 1;
    out[0] = 0.f;
}

// ---------------------------------------------------------------------------
// Fused kernel: blocks [0,32) = pair-step scan consumers (wave-1 resident),
// blocks [32, 32+16384) = producers, one (t,b) row each, t-major order.
// ---------------------------------------------------------------------------
__global__ __launch_bounds__(256) void fused_kernel(const float* __restrict__ acts,
                                                    const int* __restrict__ targets,
                                                    const int* __restrict__ act_lens,
                                                    const int* __restrict__ label_lens,
                                                    float* __restrict__ out) {
    const int epoch = g_epoch;
    const int tid = threadIdx.x;

    if (blockIdx.x >= NSCAN) {
        // ================= PRODUCER: one row per block =================
        const int row = blockIdx.x - NSCAN;           // t*BB + b
        const float* __restrict__ rowp = acts + (size_t)row * VV;
        const float4* __restrict__ p = (const float4*)rowp;
        __shared__ float sm[8], sv[8];
        __shared__ float sLogZ;

        float m = NEGF, s = 0.f;
        #pragma unroll 4
        for (int i = tid; i < VV/4; i += 256) {
            float4 v = p[i];
            float mx = fmaxf(fmaxf(v.x, v.y), fmaxf(v.z, v.w));
            if (mx > m) { s *= __expf(m - mx); m = mx; }
            s += __expf(v.x - m) + __expf(v.y - m) + __expf(v.z - m) + __expf(v.w - m);
        }
        #pragma unroll
        for (int off = 16; off; off >>= 1) {
            float m2 = __shfl_xor_sync(0xffffffffu, m, off);
            float s2 = __shfl_xor_sync(0xffffffffu, s, off);
            float M = fmaxf(m, m2);
            s = s * __expf(m - M) + s2 * __expf(m2 - M);
            m = M;
        }
        int w = tid >> 5;
        if ((tid & 31) == 0) { sm[w] = m; sv[w] = s; }
        __syncthreads();
        if (tid == 0) {
            float M = sm[0], Sv = sv[0];
            #pragma unroll
            for (int i = 1; i < 8; i++) {
                float m2 = sm[i], s2 = sv[i];
                float Mn = fmaxf(M, m2);
                Sv = Sv * __expf(M - Mn) + s2 * __expf(m2 - Mn);
                M = Mn;
            }
            sLogZ = M + __logf(Sv);
        }
        __syncthreads();

        // Gather 201 extended-label emissions (L1 hits), log2 domain.
        if (tid < SS) {
            int b = row % BB;
            int lab = (tid & 1) ? __ldg(&targets[b*LL + (tid >> 1)]) : 0;
            g_lp[(size_t)row * SS + tid] = (rowp[lab] - sLogZ) * LOG2E;
        }
        __syncthreads();
        if (tid == 0) st_rel(&g_flags[row], epoch);   // publish row
    } else {
        // ================= SCAN (consumer): pair-step, 2 steps/barrier ======
        const int b   = blockIdx.x;
        const int w   = tid >> 5;
        const int l   = tid & 31;
        const int s   = OWN * w + l - 4;           // state id (mirrors for l<4)
        const bool live = (s >= 0 && s < SS);
        const bool owned = (l >= 4) && live;
        const int alen = act_lens[b];

        __shared__ float bnd[2][SWARPS*4];
        __shared__ float fin[SS];

        bool cs = false;
        if (live && (s & 1)) {
            int cl = targets[b*LL + (s >> 1)];
            int pl = (s >= 3) ? targets[b*LL + ((s - 2) >> 1)] : -1;
            cs = (cl != 0) && (cl != pl);
        }

        // wait for rows 0..8 (alpha0 + first prefetch group), batched poll
        {
            int nr;
            do {
                nr = 0;
                #pragma unroll
                for (int t = 0; t <= 2*DEPTH; t++)
                    nr |= ld_acq(&g_flags[t*BB + b]) ^ epoch;
            } while (nr);
        }

        // alpha[0]
        float a = NEGF;
        if (live && s <= 1) a = g_lp[(size_t)b * SS + s];

        const int NPAIR = (TT - 2) / 2;            // 255 pairs: t = 1..510

        float ltA[DEPTH], lt1A[DEPTH], ltB[DEPTH], lt1B[DEPTH];
        #pragma unroll
        for (int j = 0; j < DEPTH; j++) {
            int t = 1 + 2*j;
            ltA[j]  = live ? g_lp[(size_t)(t*BB + b)*SS + s]     : 0.f;
            lt1A[j] = live ? g_lp[(size_t)((t+1)*BB + b)*SS + s] : 0.f;
        }
        __syncthreads();

        for (int p0 = 0; p0 < NPAIR; p0 += DEPTH) {
            // batched poll for next group's rows (all flags in one round trip)
            {
                int nr;
                do {
                    nr = 0;
                    #pragma unroll
                    for (int j = 0; j < DEPTH; j++) {
                        int pn = p0 + DEPTH + j;
                        if (pn < NPAIR) {
                            int t = 1 + 2*pn;
                            nr |= ld_acq(&g_flags[t*BB + b]) ^ epoch;
                            nr |= ld_acq(&g_flags[(t+1)*BB + b]) ^ epoch;
                        }
                    }
                } while (nr);
            }
            // prefetch next group (compile-time slot index)
            #pragma unroll
            for (int j = 0; j < DEPTH; j++) {
                int pn = p0 + DEPTH + j;
                bool ok = live && (pn < NPAIR);
                int t = 1 + 2*pn;
                ltB[j]  = ok ? g_lp[(size_t)(t*BB + b)*SS + s]     : 0.f;
                lt1B[j] = ok ? g_lp[(size_t)((t+1)*BB + b)*SS + s] : 0.f;
            }
            #pragma unroll
            for (int j = 0; j < DEPTH; j++) {
                const int p = p0 + j;
                if (p >= NPAIR) break;             // uniform
                const int t = 1 + 2*p;
                float lp_t  = ltA[j];
                float lp_t1 = lt1A[j];

                // step A: c = alpha[t][s] (valid lanes >= 2)
                float a2 = __shfl_up_sync(0xffffffffu, a, 1);
                float a3 = __shfl_up_sync(0xffffffffu, a, 2);
                float c;
                {
                    float a3e = cs ? a3 : NEGF;
                    float m = fmaxf(a, fmaxf(a2, a3e));
                    float r = ex2f(a - m) + ex2f(a2 - m) + ex2f(a3e - m);
                    c = m + lg2f(r) + lp_t;
                }
                c = (t < alen) ? c : a;
                if (!live) c = NEGF;

                // step B: nv = alpha[t+1][s] (valid lanes >= 4)
                float c2 = __shfl_up_sync(0xffffffffu, c, 1);
                float c3 = __shfl_up_sync(0xffffffffu, c, 2);
                float nv;
                {
                    float c3e = cs ? c3 : NEGF;
                    float m = fmaxf(c, fmaxf(c2, c3e));
                    float r = ex2f(c - m) + ex2f(c2 - m) + ex2f(c3e - m);
                    nv = m + lg2f(r) + lp_t1;
                }
                nv = (t + 1 < alen) ? nv : c;
                if (!live) nv = NEGF;

                if (l >= 28) bnd[j & 1][w*4 + (l - 28)] = nv;
                __syncthreads();
                if (l < 4) a = (w > 0) ? bnd[j & 1][(w - 1)*4 + l] : NEGF;
                else       a = nv;
            }
            #pragma unroll
            for (int j = 0; j < DEPTH; j++) { ltA[j] = ltB[j]; lt1A[j] = lt1B[j]; }
        }

        // tail: single step t = TT-1 = 511
        {
            const int t = TT - 1;
            while (ld_acq(&g_flags[t*BB + b]) != epoch) { }
            float lp_t = live ? g_lp[(size_t)(t*BB + b)*SS + s] : 0.f;
            float a2 = __shfl_up_sync(0xffffffffu, a, 1);
            float a3 = __shfl_up_sync(0xffffffffu, a, 2);
            float a3e = cs ? a3 : NEGF;
            float m = fmaxf(a, fmaxf(a2, a3e));
            float r = ex2f(a - m) + ex2f(a2 - m) + ex2f(a3e - m);
            float c = m + lg2f(r) + lp_t;
            a = (t < alen) ? c : a;
        }

        if (owned) fin[s] = a;
        __syncthreads();
        if (tid == 0) {
            int sl = 2 * label_lens[b];
            float x = fin[sl], y = fin[sl - 1];
            float m = fmaxf(x, y);
            float ll2 = m + lg2f(ex2f(x - m) + ex2f(y - m));   // log2 domain
            atomicAdd(out, -ll2 * (LN2 / (float)BB));
        }
    }
}

// ---------------------------------------------------------------------------
extern "C" void kernel_launch(void* const* d_in, const int* in_sizes, int n_in,
                              void* d_out, int out_size) {
    const float* acts       = (const float*)d_in[0];
    const int*   targets    = (const int*)d_in[1];
    const int*   act_lens   = (const int*)d_in[2];
    const int*   label_lens = (const int*)d_in[3];
    float* out = (float*)d_out;

    init_kernel<<<1, 1>>>(out);
    fused_kernel<<<NBLK, 256>>>(acts, targets, act_lens, label_lens, out);
}

// round 9
// speedup vs baseline: 1.6988x; 1.6988x over previous
#include <cuda_runtime.h>
#include <cuda_bf16.h>

#define TT 512
#define BB 32
#define VV 8000
#define LL 100
#define SS (2*LL+1)   // 201
#define NEGF (-1e30f)
#define LOG2E 1.4426950408889634f
#define LN2   0.6931471805599453f

#define SWARPS 9      // scan warps per sample
#define OWN   24      // owned states per warp (lanes 8..31)
#define MIR    8      // mirror lanes (0..7) = prev warp's top 8 states
#define QDEPTH 2      // quad prefetch depth (quads of 4 steps)

// Scratch (allocation-free rule: __device__ globals)
__device__ float g_lp[TT*BB*SS];      // 13.2 MB, log2-domain emissions

__device__ __forceinline__ float ex2f(float x) {
    float r; asm("ex2.approx.ftz.f32 %0, %1;" : "=f"(r) : "f"(x)); return r;
}
__device__ __forceinline__ float lg2f(float x) {
    float r; asm("lg2.approx.ftz.f32 %0, %1;" : "=f"(r) : "f"(x)); return r;
}

// ---------------------------------------------------------------------------
// K1: logZ = logsumexp over V of acts[t,b,:], then gather lp_ext for this row
//     (row L1-resident), stored in LOG2 domain. One block per (t,b) row.
// ---------------------------------------------------------------------------
__global__ __launch_bounds__(256) void logz_gather_kernel(const float* __restrict__ acts,
                                                          const int* __restrict__ targets,
                                                          float* __restrict__ out) {
    const int row = blockIdx.x;                    // t*BB + b
    const int b   = row % BB;
    const float* __restrict__ rowp = acts + (size_t)row * VV;
    const float4* __restrict__ p = (const float4*)rowp;
    const int tid = threadIdx.x;

    if (row == 0 && tid == 0) out[0] = 0.f;        // zero the batch-mean accumulator

    float m = NEGF, s = 0.f;
    #pragma unroll 4
    for (int i = tid; i < VV/4; i += 256) {
        float4 v = p[i];
        float mx = fmaxf(fmaxf(v.x, v.y), fmaxf(v.z, v.w));
        if (mx > m) { s *= __expf(m - mx); m = mx; }
        s += __expf(v.x - m) + __expf(v.y - m) + __expf(v.z - m) + __expf(v.w - m);
    }
    #pragma unroll
    for (int off = 16; off; off >>= 1) {
        float m2 = __shfl_xor_sync(0xffffffffu, m, off);
        float s2 = __shfl_xor_sync(0xffffffffu, s, off);
        float M = fmaxf(m, m2);
        s = s * __expf(m - M) + s2 * __expf(m2 - M);
        m = M;
    }
    __shared__ float sm[8], sv[8];
    __shared__ float sLogZ;
    int w = tid >> 5;
    if ((tid & 31) == 0) { sm[w] = m; sv[w] = s; }
    __syncthreads();
    if (tid == 0) {
        float M = sm[0], Sv = sv[0];
        #pragma unroll
        for (int i = 1; i < 8; i++) {
            float m2 = sm[i], s2 = sv[i];
            float Mn = fmaxf(M, m2);
            Sv = Sv * __expf(M - Mn) + s2 * __expf(m2 - Mn);
            M = Mn;
        }
        sLogZ = M + __logf(Sv);
    }
    __syncthreads();

    // Gather 201 extended-label emissions (L1 hits), scale to log2 domain.
    if (tid < SS) {
        int lab = (tid & 1) ? __ldg(&targets[b*LL + (tid >> 1)]) : 0;
        g_lp[(size_t)row * SS + tid] = (rowp[lab] - sLogZ) * LOG2E;
    }
}

// ---------------------------------------------------------------------------
// K2: alpha scan, FOUR time-steps per barrier.
//     Warp w: lanes 8..31 own states 24w..24w+23; lanes 0..7 mirror the
//     previous warp's top 8 states. Mirror validity erodes 2 lanes/step;
//     after 4 steps owned lanes (>=8) are still exact. One boundary exchange
//     + one __syncthreads per quad. All prefetch slots compile-time indexed.
// ---------------------------------------------------------------------------
__global__ __launch_bounds__(32*SWARPS) void scan_kernel(const int* __restrict__ targets,
                                                         const int* __restrict__ act_lens,
                                                         const int* __restrict__ label_lens,
                                                         float* __restrict__ out) {
    const int b   = blockIdx.x;
    const int tid = threadIdx.x;
    const int w   = tid >> 5;
    const int l   = tid & 31;
    const int s   = OWN * w + l - MIR;         // state id (mirrors for l<8)
    const bool live = (s >= 0 && s < SS);
    const bool owned = (l >= MIR) && live;
    const int alen = act_lens[b];

    __shared__ float bnd[2][SWARPS*MIR];       // boundary states, double-buffered
    __shared__ float fin[SS];

    bool cs = false;                           // can_skip (odd states only)
    if (live && (s & 1)) {
        int cl = targets[b*LL + (s >> 1)];
        int pl = (s >= 3) ? targets[b*LL + ((s - 2) >> 1)] : -1;
        cs = (cl != 0) && (cl != pl);
    }

    // one DP step in log2 domain
    auto step = [&](float av, float lp, int t) -> float {
        float x2 = __shfl_up_sync(0xffffffffu, av, 1);
        float x3 = __shfl_up_sync(0xffffffffu, av, 2);
        float x3e = cs ? x3 : NEGF;
        float m = fmaxf(av, fmaxf(x2, x3e));
        float r = ex2f(av - m) + ex2f(x2 - m) + ex2f(x3e - m);
        float nv = m + lg2f(r) + lp;
        nv = (t < alen) ? nv : av;
        return live ? nv : NEGF;
    };

    // alpha[0]
    float a = NEGF;
    if (live && s <= 1) a = g_lp[(size_t)b * SS + s];

    // quads: quad q covers t = 1+4q .. 4+4q, q = 0..126  (t up to 508)
    const int NQUAD = 127;

    // tail lp (t = 509, 510, 511) prefetched up-front
    float ltl0 = live ? g_lp[(size_t)(509*BB + b)*SS + s] : 0.f;
    float ltl1 = live ? g_lp[(size_t)(510*BB + b)*SS + s] : 0.f;
    float ltl2 = live ? g_lp[(size_t)(511*BB + b)*SS + s] : 0.f;

    // lp prefetch: QDEPTH quads (8 steps), compile-time slots only
    float lqA[4*QDEPTH], lqB[4*QDEPTH];
    #pragma unroll
    for (int j = 0; j < 4*QDEPTH; j++) {
        int t = 1 + j;
        lqA[j] = live ? g_lp[(size_t)(t*BB + b)*SS + s] : 0.f;
    }
    __syncthreads();

    for (int q0 = 0; q0 < NQUAD; q0 += QDEPTH) {
        // prefetch next group (compile-time slot index)
        #pragma unroll
        for (int j = 0; j < 4*QDEPTH; j++) {
            int t = 1 + 4*(q0 + QDEPTH) + j;
            bool ok = live && (t <= 508);
            lqB[j] = ok ? g_lp[(size_t)(t*BB + b)*SS + s] : 0.f;
        }
        #pragma unroll
        for (int jq = 0; jq < QDEPTH; jq++) {
            const int q = q0 + jq;
            if (q >= NQUAD) break;             // uniform across block
            const int t = 1 + 4*q;

            float v1 = step(a,  lqA[4*jq + 0], t);
            float v2 = step(v1, lqA[4*jq + 1], t + 1);
            float v3 = step(v2, lqA[4*jq + 2], t + 2);
            float v4 = step(v3, lqA[4*jq + 3], t + 3);

            // boundary exchange: top 8 owned states -> next warp's mirrors
            if (l >= 32 - MIR) bnd[jq][w*MIR + (l - (32 - MIR))] = v4;
            __syncthreads();
            if (l < MIR) a = (w > 0) ? bnd[jq][(w - 1)*MIR + l] : NEGF;
            else         a = v4;
        }
        #pragma unroll
        for (int j = 0; j < 4*QDEPTH; j++) lqA[j] = lqB[j];
    }

    // tail: t = 509, 510, 511 — one step per barrier (mirror refresh each step)
    {
        float d = step(a, ltl0, 509);
        if (l >= 32 - MIR) bnd[1][w*MIR + (l - (32 - MIR))] = d;
        __syncthreads();
        a = (l < MIR) ? ((w > 0) ? bnd[1][(w - 1)*MIR + l] : NEGF) : d;

        d = step(a, ltl1, 510);
        if (l >= 32 - MIR) bnd[0][w*MIR + (l - (32 - MIR))] = d;
        __syncthreads();
        a = (l < MIR) ? ((w > 0) ? bnd[0][(w - 1)*MIR + l] : NEGF) : d;

        a = step(a, ltl2, 511);
    }

    if (owned) fin[s] = a;
    __syncthreads();
    if (tid == 0) {
        int sl = 2 * label_lens[b];
        float x = fin[sl], y = fin[sl - 1];
        float m = fmaxf(x, y);
        float ll2 = m + lg2f(ex2f(x - m) + ex2f(y - m));   // log2 domain
        atomicAdd(out, -ll2 * (LN2 / (float)BB));
    }
}

// ---------------------------------------------------------------------------
extern "C" void kernel_launch(void* const* d_in, const int* in_sizes, int n_in,
                              void* d_out, int out_size) {
    const float* acts       = (const float*)d_in[0];
    const int*   targets    = (const int*)d_in[1];
    const int*   act_lens   = (const int*)d_in[2];
    const int*   label_lens = (const int*)d_in[3];
    float* out = (float*)d_out;

    logz_gather_kernel<<<TT*BB, 256>>>(acts, targets, out);
    scan_kernel<<<BB, 32*SWARPS>>>(targets, act_lens, label_lens, out);
}